// round 4
// baseline (speedup 1.0000x reference)
#include <cuda_runtime.h>
#include <math.h>

// Problem constants (fixed by reference setup_inputs)
#define N_BATCH 256
#define M_ROWS  8
#define T_LEN   16384
#define THREADS 256
#define NWARPS  (THREADS / 32)
#define T4      (T_LEN / 4)              // 4096 float4 per row
#define ITERS   (T4 / THREADS)           // 16 stages of work
#define STAGES  3                        // cp.async pipeline depth
#define NACC    30                       // band |m-k| <= 4 of the 8x8 Gram

// acc layout: band[d][i] = C[i+d][i], d=0..4, i=0..7-d
__device__ __constant__ int c_off[5] = {0, 8, 15, 21, 26};

#define CPA16(dst, src) \
    asm volatile("cp.async.cg.shared.global [%0], [%1], 16;" \
                 :: "r"(dst), "l"(src) : "memory")
#define CPA_COMMIT() asm volatile("cp.async.commit_group;" ::: "memory")
#define CPA_WAIT2()  asm volatile("cp.async.wait_group 2;" ::: "memory")

__device__ __forceinline__ unsigned smem_addr(const void* p) {
    return (unsigned)__cvta_generic_to_shared(p);
}

__global__ void __launch_bounds__(THREADS, 2)
ssf_kernel(const float* __restrict__ X, float* __restrict__ out) {
    extern __shared__ float4 buf[];      // [STAGES][M_ROWS][THREADS]
    __shared__ float sred[NWARPS][NACC];
    __shared__ float sC[NACC];

    const int n   = blockIdx.x;
    const int tid = threadIdx.x;
    const float4* __restrict__ base =
        reinterpret_cast<const float4*>(X + (size_t)n * M_ROWS * T_LEN);

    // ---- prologue: fill all STAGES ----
#pragma unroll
    for (int s = 0; s < STAGES; s++) {
        const float4* col = base + s * THREADS + tid;
#pragma unroll
        for (int m = 0; m < M_ROWS; m++)
            CPA16(smem_addr(&buf[(s * M_ROWS + m) * THREADS + tid]),
                  col + m * T4);
        CPA_COMMIT();
    }

    float acc[NACC];
#pragma unroll
    for (int i = 0; i < NACC; i++) acc[i] = 0.f;

    // ---- main loop: no barriers (each thread consumes its own bytes) ----
#pragma unroll 1
    for (int it = 0; it < ITERS; it++) {
        CPA_WAIT2();                      // stage `it` has landed
        const int sb = it % STAGES;

        float4 x[M_ROWS];
#pragma unroll
        for (int m = 0; m < M_ROWS; m++)
            x[m] = buf[(sb * M_ROWS + m) * THREADS + tid];

#pragma unroll
        for (int m = 0; m < M_ROWS; m++) {
            const int dmax = (m < 4) ? m : 4;
#pragma unroll
            for (int d = 0; d <= dmax; d++) {
                const int ai = c_off[d] + (m - d);
                acc[ai] = fmaf(x[m].x, x[m - d].x, acc[ai]);
                acc[ai] = fmaf(x[m].y, x[m - d].y, acc[ai]);
                acc[ai] = fmaf(x[m].z, x[m - d].z, acc[ai]);
                acc[ai] = fmaf(x[m].w, x[m - d].w, acc[ai]);
            }
        }

        // refill this buffer slot with stage it+STAGES (if any)
        const int nit = it + STAGES;
        if (nit < ITERS) {
            const float4* col = base + nit * THREADS + tid;
            const int sb2 = nit % STAGES;
#pragma unroll
            for (int m = 0; m < M_ROWS; m++)
                CPA16(smem_addr(&buf[(sb2 * M_ROWS + m) * THREADS + tid]),
                      col + m * T4);
        }
        CPA_COMMIT();                     // always one group per iter
    }

    // ---- reduce 30 sums across the CTA ----
#pragma unroll
    for (int i = 0; i < NACC; i++) {
#pragma unroll
        for (int off = 16; off > 0; off >>= 1)
            acc[i] += __shfl_down_sync(0xffffffffu, acc[i], off);
    }
    const int warp = tid >> 5;
    const int lane = tid & 31;
    if (lane == 0) {
#pragma unroll
        for (int i = 0; i < NACC; i++) sred[warp][i] = acc[i];
    }
    __syncthreads();

    if (tid < NACC) {
        float s = 0.f;
#pragma unroll
        for (int w = 0; w < NWARPS; w++) s += sred[w][tid];
        sC[tid] = s * (1.0f / (float)T_LEN);   // banded C = Gram / T
    }
    __syncthreads();

    if (tid == 0) {
        // tri(s1,s2) = 1/4 * sum_j C[j+s2][j+s1] = 1/4 * sum_j band[d][j+s1],
        // d = s2-s1, in jnp.triu_indices(5) row-major order.
        float tri[15];
        int p = 0;
#pragma unroll
        for (int s1 = 0; s1 < 5; s1++) {
#pragma unroll
            for (int s2 = s1; s2 < 5; s2++) {
                const int d = s2 - s1;
                float r = 0.f;
#pragma unroll
                for (int j = 0; j < 4; j++)
                    r += sC[c_off[d] + j + s1];
                tri[p++] = r * 0.25f;
            }
        }

        // feat = [tri (15), zeros (15)]; standardize over all 30 (pop. std)
        float mean = 0.f;
#pragma unroll
        for (int i = 0; i < 15; i++) mean += tri[i];
        mean *= (1.0f / 30.0f);

        float var = 0.f;
#pragma unroll
        for (int i = 0; i < 15; i++) {
            const float dd = tri[i] - mean;
            var += dd * dd;
        }
        var += 15.0f * mean * mean;    // 15 zero entries contribute mean^2
        var *= (1.0f / 30.0f);

        const float inv = 1.0f / (sqrtf(var) + 1e-8f);

        float* o = out + n * 30;
#pragma unroll
        for (int i = 0; i < 15; i++) o[i] = (tri[i] - mean) * inv;
        const float zval = -mean * inv;
#pragma unroll
        for (int i = 15; i < 30; i++) o[i] = zval;
    }
}

extern "C" void kernel_launch(void* const* d_in, const int* in_sizes, int n_in,
                              void* d_out, int out_size) {
    const float* X = (const float*)d_in[0];
    float* out = (float*)d_out;

    const int smem_bytes = STAGES * M_ROWS * THREADS * (int)sizeof(float4); // 96 KB
    cudaFuncSetAttribute(ssf_kernel,
                         cudaFuncAttributeMaxDynamicSharedMemorySize,
                         smem_bytes);
    ssf_kernel<<<N_BATCH, THREADS, smem_bytes>>>(X, out);
}

// round 5
// speedup vs baseline: 3.0937x; 3.0937x over previous
#include <cuda_runtime.h>
#include <math.h>

// Problem constants (fixed by reference setup_inputs)
#define N_BATCH 256
#define M_ROWS  8
#define T_LEN   16384
#define THREADS 512
#define NWARPS  (THREADS / 32)
#define TV      (T_LEN / 4)              // 4096 x 16B vectors per row
#define ITERS   (TV / THREADS)           // 8
#define NACC    30                       // band |m-k| <= 4 of the 8x8 Gram

typedef unsigned long long u64;

// Packed f32x2 FMA / ADD (sm_100+; ptxas never emits FFMA2 from plain C++)
#define FMA2(d, a, b, c) \
    asm("fma.rn.f32x2 %0, %1, %2, %3;" : "=l"(d) : "l"(a), "l"(b), "l"(c))
#define ADD2(d, a, b) \
    asm("add.rn.f32x2 %0, %1, %2;" : "=l"(d) : "l"(a), "l"(b))
#define UNPACK2(lo, hi, v) \
    asm("mov.b64 {%0, %1}, %2;" : "=f"(lo), "=f"(hi) : "l"(v))

// band layout: acc[c_off(d) + k] holds sum_t X[k+d][t] * X[k][t]
__host__ __device__ __forceinline__ constexpr int c_off(int d) {
    return (d == 0) ? 0 : (d == 1) ? 8 : (d == 2) ? 15 : (d == 3) ? 21 : 26;
}

__global__ void __launch_bounds__(THREADS)
ssf_kernel(const float* __restrict__ X, float* __restrict__ out) {
    __shared__ float sred[NWARPS][NACC];
    __shared__ float sC[NACC];

    const int n   = blockIdx.x;
    const int tid = threadIdx.x;

    const ulonglong2* __restrict__ base =
        reinterpret_cast<const ulonglong2*>(X + (size_t)n * M_ROWS * T_LEN);

    u64 acc[NACC];
#pragma unroll
    for (int i = 0; i < NACC; i++) acc[i] = 0ull;   // packed {+0.f, +0.f}

#pragma unroll 2
    for (int it = 0; it < ITERS; it++) {
        const int tv = tid + it * THREADS;
        u64 lo[M_ROWS], hi[M_ROWS];
#pragma unroll
        for (int m = 0; m < M_ROWS; m++) {
            const ulonglong2 v = __ldcs(base + m * TV + tv);  // one LDG.128
            lo[m] = v.x;                                      // floats {t, t+1}
            hi[m] = v.y;                                      // floats {t+2, t+3}
        }

#pragma unroll
        for (int m = 0; m < M_ROWS; m++) {
            const int dmax = (m < 4) ? m : 4;
#pragma unroll
            for (int d = 0; d <= dmax; d++) {
                const int ai = c_off(d) + (m - d);
                FMA2(acc[ai], lo[m], lo[m - d], acc[ai]);
                FMA2(acc[ai], hi[m], hi[m - d], acc[ai]);
            }
        }
    }

    // ---- intra-warp tree reduce (packed), then unpack lo+hi ----
#pragma unroll
    for (int i = 0; i < NACC; i++) {
#pragma unroll
        for (int off = 16; off > 0; off >>= 1) {
            const u64 o = __shfl_down_sync(0xffffffffu, acc[i], off);
            ADD2(acc[i], acc[i], o);
        }
    }

    const int warp = tid >> 5;
    const int lane = tid & 31;
    if (lane == 0) {
#pragma unroll
        for (int i = 0; i < NACC; i++) {
            float a, b;
            UNPACK2(a, b, acc[i]);
            sred[warp][i] = a + b;
        }
    }
    __syncthreads();

    if (tid < NACC) {
        float s = 0.f;
#pragma unroll
        for (int w = 0; w < NWARPS; w++) s += sred[w][tid];
        sC[tid] = s * (1.0f / (float)T_LEN);   // banded C = Gram / T
    }
    __syncthreads();

    if (tid == 0) {
        // tri(s1,s2) = 1/4 * sum_j C[j+s2][j+s1] = 1/4 * sum_j band[d][j+s1],
        // d = s2-s1, in jnp.triu_indices(5) row-major order.
        float tri[15];
        int p = 0;
#pragma unroll
        for (int s1 = 0; s1 < 5; s1++) {
#pragma unroll
            for (int s2 = s1; s2 < 5; s2++) {
                const int d = s2 - s1;
                float r = 0.f;
#pragma unroll
                for (int j = 0; j < 4; j++)
                    r += sC[c_off(d) + j + s1];
                tri[p++] = r * 0.25f;
            }
        }

        // feat = [tri (15), zeros (15)]; standardize over all 30 (pop. std)
        float mean = 0.f;
#pragma unroll
        for (int i = 0; i < 15; i++) mean += tri[i];
        mean *= (1.0f / 30.0f);

        float var = 0.f;
#pragma unroll
        for (int i = 0; i < 15; i++) {
            const float dd = tri[i] - mean;
            var += dd * dd;
        }
        var += 15.0f * mean * mean;    // 15 zero entries contribute mean^2
        var *= (1.0f / 30.0f);

        const float inv = 1.0f / (sqrtf(var) + 1e-8f);

        float* o = out + n * 30;
#pragma unroll
        for (int i = 0; i < 15; i++) o[i] = (tri[i] - mean) * inv;
        const float zval = -mean * inv;
#pragma unroll
        for (int i = 15; i < 30; i++) o[i] = zval;
    }
}

extern "C" void kernel_launch(void* const* d_in, const int* in_sizes, int n_in,
                              void* d_out, int out_size) {
    const float* X = (const float*)d_in[0];
    float* out = (float*)d_out;
    ssf_kernel<<<N_BATCH, THREADS>>>(X, out);
}

// round 6
// speedup vs baseline: 3.2425x; 1.0481x over previous
#include <cuda_runtime.h>
#include <math.h>

// Problem constants (fixed by reference setup_inputs)
#define N_BATCH 256
#define M_ROWS  8
#define T_LEN   16384
#define THREADS 512
#define NWARPS  (THREADS / 32)
#define TV      (T_LEN / 4)              // 4096 x 16B vectors per row
#define ITERS   (TV / THREADS)           // 8
#define NACC    30                       // band |m-k| <= 4 of the 8x8 Gram

typedef unsigned long long u64;

// Packed f32x2 FMA / ADD (sm_100+; ptxas never emits these from plain C++)
#define FMA2(d, a, b, c) \
    asm("fma.rn.f32x2 %0, %1, %2, %3;" : "=l"(d) : "l"(a), "l"(b), "l"(c))
#define ADD2(d, a, b) \
    asm("add.rn.f32x2 %0, %1, %2;" : "=l"(d) : "l"(a), "l"(b))
#define UNPACK2(lo, hi, v) \
    asm("mov.b64 {%0, %1}, %2;" : "=f"(lo), "=f"(hi) : "l"(v))

// band layout: acc[c_off(d) + k] holds sum_t X[k+d][t] * X[k][t]
__host__ __device__ __forceinline__ constexpr int c_off(int d) {
    return (d == 0) ? 0 : (d == 1) ? 8 : (d == 2) ? 15 : (d == 3) ? 21 : 26;
}

__global__ void __launch_bounds__(THREADS)
ssf_kernel(const float* __restrict__ X, float* __restrict__ out) {
    __shared__ float sred[NWARPS][NACC];
    __shared__ float sC[NACC];

    const int n   = blockIdx.x;
    const int tid = threadIdx.x;

    const ulonglong2* __restrict__ base =
        reinterpret_cast<const ulonglong2*>(X + (size_t)n * M_ROWS * T_LEN);

    u64 acc[NACC];
#pragma unroll
    for (int i = 0; i < NACC; i++) acc[i] = 0ull;   // packed {+0.f, +0.f}

    // Fully unrolled: ptxas software-pipelines the 64 LDG.128s (proven in R2)
#pragma unroll
    for (int it = 0; it < ITERS; it++) {
        const int tv = tid + it * THREADS;
        u64 lo[M_ROWS], hi[M_ROWS];
#pragma unroll
        for (int m = 0; m < M_ROWS; m++) {
            const ulonglong2 v = base[m * TV + tv];   // one LDG.128
            lo[m] = v.x;                              // floats {t,   t+1}
            hi[m] = v.y;                              // floats {t+2, t+3}
        }

#pragma unroll
        for (int m = 0; m < M_ROWS; m++) {
            const int dmax = (m < 4) ? m : 4;
#pragma unroll
            for (int d = 0; d <= dmax; d++) {
                const int ai = c_off(d) + (m - d);
                FMA2(acc[ai], lo[m], lo[m - d], acc[ai]);
                FMA2(acc[ai], hi[m], hi[m - d], acc[ai]);
            }
        }
    }

    // ---- intra-warp tree reduce (packed), then unpack lo+hi ----
#pragma unroll
    for (int i = 0; i < NACC; i++) {
#pragma unroll
        for (int off = 16; off > 0; off >>= 1) {
            const u64 o = __shfl_down_sync(0xffffffffu, acc[i], off);
            ADD2(acc[i], acc[i], o);
        }
    }

    const int warp = tid >> 5;
    const int lane = tid & 31;
    if (lane == 0) {
#pragma unroll
        for (int i = 0; i < NACC; i++) {
            float a, b;
            UNPACK2(a, b, acc[i]);
            sred[warp][i] = a + b;
        }
    }
    __syncthreads();

    if (tid < NACC) {
        float s = 0.f;
#pragma unroll
        for (int w = 0; w < NWARPS; w++) s += sred[w][tid];
        sC[tid] = s * (1.0f / (float)T_LEN);   // banded C = Gram / T
    }
    __syncthreads();

    if (tid == 0) {
        // tri(s1,s2) = 1/4 * sum_j C[j+s2][j+s1] = 1/4 * sum_j band[d][j+s1],
        // d = s2-s1, in jnp.triu_indices(5) row-major order.
        float tri[15];
        int p = 0;
#pragma unroll
        for (int s1 = 0; s1 < 5; s1++) {
#pragma unroll
            for (int s2 = s1; s2 < 5; s2++) {
                const int d = s2 - s1;
                float r = 0.f;
#pragma unroll
                for (int j = 0; j < 4; j++)
                    r += sC[c_off(d) + j + s1];
                tri[p++] = r * 0.25f;
            }
        }

        // feat = [tri (15), zeros (15)]; standardize over all 30 (pop. std)
        float mean = 0.f;
#pragma unroll
        for (int i = 0; i < 15; i++) mean += tri[i];
        mean *= (1.0f / 30.0f);

        float var = 0.f;
#pragma unroll
        for (int i = 0; i < 15; i++) {
            const float dd = tri[i] - mean;
            var += dd * dd;
        }
        var += 15.0f * mean * mean;    // 15 zero entries contribute mean^2
        var *= (1.0f / 30.0f);

        const float inv = 1.0f / (sqrtf(var) + 1e-8f);

        float* o = out + n * 30;
#pragma unroll
        for (int i = 0; i < 15; i++) o[i] = (tri[i] - mean) * inv;
        const float zval = -mean * inv;
#pragma unroll
        for (int i = 15; i < 30; i++) o[i] = zval;
    }
}

extern "C" void kernel_launch(void* const* d_in, const int* in_sizes, int n_in,
                              void* d_out, int out_size) {
    const float* X = (const float*)d_in[0];
    float* out = (float*)d_out;
    ssf_kernel<<<N_BATCH, THREADS>>>(X, out);
}